// round 1
// baseline (speedup 1.0000x reference)
#include <cuda_runtime.h>
#include <math.h>

#define B_   2
#define T_   2048
#define D_   512
#define H_   8
#define DH_  64
#define M_   (B_*T_)   // 4096 token rows

// Scratch (no cudaMalloc allowed): 5 x 8MB fp32 buffers
__device__ float g_h[M_*D_];
__device__ float g_q[M_*D_];
__device__ float g_k[M_*D_];
__device__ float g_v[M_*D_];
__device__ float g_ctx[M_*D_];

// ---------------------------------------------------------------------------
// 1) LayerNorm: one block per token row, 256 threads x 2 elems
// ---------------------------------------------------------------------------
__global__ __launch_bounds__(256) void ln_kernel(const float* __restrict__ x,
                                                 const float* __restrict__ gamma,
                                                 const float* __restrict__ beta) {
    int row = blockIdx.x;
    int tid = threadIdx.x;
    const float* xr = x + (size_t)row * D_;
    float v0 = xr[tid], v1 = xr[tid + 256];
    float s  = v0 + v1;
    float s2 = v0 * v0 + v1 * v1;
    #pragma unroll
    for (int o = 16; o > 0; o >>= 1) {
        s  += __shfl_xor_sync(0xFFFFFFFFu, s,  o);
        s2 += __shfl_xor_sync(0xFFFFFFFFu, s2, o);
    }
    __shared__ float rs[8], rs2[8];
    int wid = tid >> 5, lane = tid & 31;
    if (lane == 0) { rs[wid] = s; rs2[wid] = s2; }
    __syncthreads();
    if (wid == 0) {
        s  = (lane < 8) ? rs[lane]  : 0.f;
        s2 = (lane < 8) ? rs2[lane] : 0.f;
        #pragma unroll
        for (int o = 4; o > 0; o >>= 1) {
            s  += __shfl_xor_sync(0xFFFFFFFFu, s,  o);
            s2 += __shfl_xor_sync(0xFFFFFFFFu, s2, o);
        }
        if (lane == 0) { rs[0] = s; rs2[0] = s2; }
    }
    __syncthreads();
    float mean = rs[0] * (1.0f / D_);
    float var  = rs2[0] * (1.0f / D_) - mean * mean;
    float rstd = rsqrtf(var + 1e-3f);
    float* hr = g_h + (size_t)row * D_;
    hr[tid]       = (v0 - mean) * rstd * gamma[tid]       + beta[tid];
    hr[tid + 256] = (v1 - mean) * rstd * gamma[tid + 256] + beta[tid + 256];
}

// ---------------------------------------------------------------------------
// 2/4) fp32 tiled GEMM: C[M,512] = A[M,512] @ B[512,512] (+bias)(+resid)
//      BM=128, BN=64, BK=16, 256 threads, 8x4 register tile per thread
// ---------------------------------------------------------------------------
#define BM 128
#define BN 64
#define BK 16

template <bool RESID>
__device__ __forceinline__ void gemm_body(const float* __restrict__ A,
                                          const float* __restrict__ Bmat,
                                          const float* __restrict__ bias,
                                          const float* __restrict__ resid,
                                          float* __restrict__ C,
                                          int bx, int by) {
    __shared__ float As[BK][BM + 4];   // row = 132 floats = 528B (16B multiple)
    __shared__ float Bs[BK][BN + 4];   // row = 68 floats  = 272B (16B multiple)
    const int K = D_, N = D_;
    int tid = threadIdx.x;
    int tx = tid & 15;          // N-dim: 16 threads x 4 cols
    int ty = tid >> 4;          // M-dim: 16 threads x 8 rows
    int m0 = by * BM, n0 = bx * BN;

    float acc[8][4];
    #pragma unroll
    for (int i = 0; i < 8; i++)
        #pragma unroll
        for (int j = 0; j < 4; j++) acc[i][j] = 0.f;

    for (int k0 = 0; k0 < K; k0 += BK) {
        // Load A tile: 128x16 = 512 float4, 2 per thread
        #pragma unroll
        for (int i = 0; i < 2; i++) {
            int idx = tid + i * 256;
            int row = idx >> 2;               // 0..127
            int kq  = (idx & 3) << 2;         // 0,4,8,12
            float4 av = *(const float4*)(A + (size_t)(m0 + row) * K + k0 + kq);
            As[kq + 0][row] = av.x;
            As[kq + 1][row] = av.y;
            As[kq + 2][row] = av.z;
            As[kq + 3][row] = av.w;
        }
        // Load B tile: 16x64 = 256 float4, 1 per thread
        {
            int row = tid >> 4;               // k 0..15
            int nq  = (tid & 15) << 2;        // 0..60
            float4 bv = *(const float4*)(Bmat + (size_t)(k0 + row) * N + n0 + nq);
            Bs[row][nq + 0] = bv.x;
            Bs[row][nq + 1] = bv.y;
            Bs[row][nq + 2] = bv.z;
            Bs[row][nq + 3] = bv.w;
        }
        __syncthreads();
        #pragma unroll
        for (int kk = 0; kk < BK; kk++) {
            float4 a0 = *(const float4*)&As[kk][ty * 8];
            float4 a1 = *(const float4*)&As[kk][ty * 8 + 4];
            float4 b0 = *(const float4*)&Bs[kk][tx * 4];
            float a[8] = {a0.x, a0.y, a0.z, a0.w, a1.x, a1.y, a1.z, a1.w};
            float b[4] = {b0.x, b0.y, b0.z, b0.w};
            #pragma unroll
            for (int i = 0; i < 8; i++)
                #pragma unroll
                for (int j = 0; j < 4; j++)
                    acc[i][j] = fmaf(a[i], b[j], acc[i][j]);
        }
        __syncthreads();
    }

    int n = n0 + tx * 4;
    float4 bias4 = *(const float4*)(bias + n);
    #pragma unroll
    for (int i = 0; i < 8; i++) {
        int m = m0 + ty * 8 + i;
        float4 o;
        o.x = acc[i][0] + bias4.x;
        o.y = acc[i][1] + bias4.y;
        o.z = acc[i][2] + bias4.z;
        o.w = acc[i][3] + bias4.w;
        if (RESID) {
            float4 r = *(const float4*)(resid + (size_t)m * N + n);
            o.x += r.x; o.y += r.y; o.z += r.z; o.w += r.w;
        }
        *(float4*)(C + (size_t)m * N + n) = o;
    }
}

__global__ __launch_bounds__(256) void qkv_kernel(const float* __restrict__ Wq,
                                                  const float* __restrict__ bq,
                                                  const float* __restrict__ Wk,
                                                  const float* __restrict__ bk,
                                                  const float* __restrict__ Wv,
                                                  const float* __restrict__ bv) {
    const float* W; const float* bi; float* C;
    if (blockIdx.z == 0)      { W = Wq; bi = bq; C = g_q; }
    else if (blockIdx.z == 1) { W = Wk; bi = bk; C = g_k; }
    else                      { W = Wv; bi = bv; C = g_v; }
    gemm_body<false>(g_h, W, bi, nullptr, C, blockIdx.x, blockIdx.y);
}

__global__ __launch_bounds__(256) void out_kernel(const float* __restrict__ Wo,
                                                  const float* __restrict__ bo,
                                                  const float* __restrict__ x,
                                                  float* __restrict__ out) {
    gemm_body<true>(g_ctx, Wo, bo, x, out, blockIdx.x, blockIdx.y);
}

// ---------------------------------------------------------------------------
// 3) Banded attention: one warp per (b,t,h); window [max(t-6,0), min(t+3,T-1)]
// ---------------------------------------------------------------------------
__global__ __launch_bounds__(256) void attn_kernel() {
    int gwarp = (blockIdx.x * blockDim.x + threadIdx.x) >> 5;
    int lane  = threadIdx.x & 31;
    int h  = gwarp & 7;
    int bt = gwarp >> 3;                 // 0..4095
    int b  = bt >> 11;
    int t  = bt & 2047;
    int lo = max(t - 6, 0);
    int hi = min(t + 3, T_ - 1);
    int nw = hi - lo + 1;                // <= 10

    const float* qp = g_q + (size_t)bt * D_ + h * DH_;
    float q0 = qp[lane], q1 = qp[lane + 32];

    float sc[10];
    float mx = -1e30f;
    for (int jj = 0; jj < nw; jj++) {
        int j = lo + jj;
        const float* kp = g_k + ((size_t)(b * T_ + j)) * D_ + h * DH_;
        float s = q0 * kp[lane] + q1 * kp[lane + 32];
        #pragma unroll
        for (int o = 16; o > 0; o >>= 1) s += __shfl_xor_sync(0xFFFFFFFFu, s, o);
        s *= 0.125f;                     // 1/sqrt(64)
        sc[jj] = s;
        mx = fmaxf(mx, s);
    }
    float denom = 0.f, c0 = 0.f, c1 = 0.f;
    for (int jj = 0; jj < nw; jj++) {
        int j = lo + jj;
        float p = __expf(sc[jj] - mx);
        denom += p;
        const float* vp = g_v + ((size_t)(b * T_ + j)) * D_ + h * DH_;
        c0 = fmaf(p, vp[lane],      c0);
        c1 = fmaf(p, vp[lane + 32], c1);
    }
    float inv = 1.f / denom;
    float* cp = g_ctx + (size_t)bt * D_ + h * DH_;
    cp[lane]      = c0 * inv;
    cp[lane + 32] = c1 * inv;
}

// ---------------------------------------------------------------------------
// Launch
// ---------------------------------------------------------------------------
extern "C" void kernel_launch(void* const* d_in, const int* in_sizes, int n_in,
                              void* d_out, int out_size) {
    const float* x     = (const float*)d_in[0];
    const float* gamma = (const float*)d_in[1];
    const float* beta  = (const float*)d_in[2];
    const float* Wq    = (const float*)d_in[3];
    const float* bq    = (const float*)d_in[4];
    const float* Wk    = (const float*)d_in[5];
    const float* bk    = (const float*)d_in[6];
    const float* Wv    = (const float*)d_in[7];
    const float* bv    = (const float*)d_in[8];
    const float* Wo    = (const float*)d_in[9];
    const float* bo    = (const float*)d_in[10];
    float* out = (float*)d_out;

    ln_kernel<<<M_, 256>>>(x, gamma, beta);
    qkv_kernel<<<dim3(D_/BN, M_/BM, 3), 256>>>(Wq, bq, Wk, bk, Wv, bv);
    attn_kernel<<<(M_*H_)/8, 256>>>();
    out_kernel<<<dim3(D_/BN, M_/BM), 256>>>(Wo, bo, x, out);
}

// round 2
// speedup vs baseline: 1.6191x; 1.6191x over previous
#include <cuda_runtime.h>
#include <math.h>
#include <stdint.h>

#define B_   2
#define T_   2048
#define D_   512
#define H_   8
#define DH_  64
#define M_   (B_*T_)   // 4096 token rows

// Scratch (no cudaMalloc allowed)
__device__ float g_h[M_*D_];
__device__ float g_q[M_*D_];
__device__ float g_k[M_*D_];
__device__ float g_v[M_*D_];
__device__ float g_ctx[M_*D_];

// ---------------------------------------------------------------------------
// 1) LayerNorm: one block per token row
// ---------------------------------------------------------------------------
__global__ __launch_bounds__(256) void ln_kernel(const float* __restrict__ x,
                                                 const float* __restrict__ gamma,
                                                 const float* __restrict__ beta) {
    int row = blockIdx.x;
    int tid = threadIdx.x;
    const float* xr = x + (size_t)row * D_;
    float v0 = xr[tid], v1 = xr[tid + 256];
    float s  = v0 + v1;
    float s2 = v0 * v0 + v1 * v1;
    #pragma unroll
    for (int o = 16; o > 0; o >>= 1) {
        s  += __shfl_xor_sync(0xFFFFFFFFu, s,  o);
        s2 += __shfl_xor_sync(0xFFFFFFFFu, s2, o);
    }
    __shared__ float rs[8], rs2[8];
    int wid = tid >> 5, lane = tid & 31;
    if (lane == 0) { rs[wid] = s; rs2[wid] = s2; }
    __syncthreads();
    if (wid == 0) {
        s  = (lane < 8) ? rs[lane]  : 0.f;
        s2 = (lane < 8) ? rs2[lane] : 0.f;
        #pragma unroll
        for (int o = 4; o > 0; o >>= 1) {
            s  += __shfl_xor_sync(0xFFFFFFFFu, s,  o);
            s2 += __shfl_xor_sync(0xFFFFFFFFu, s2, o);
        }
        if (lane == 0) { rs[0] = s; rs2[0] = s2; }
    }
    __syncthreads();
    float mean = rs[0] * (1.0f / D_);
    float var  = rs2[0] * (1.0f / D_) - mean * mean;
    float rstd = rsqrtf(var + 1e-3f);
    float* hr = g_h + (size_t)row * D_;
    hr[tid]       = (v0 - mean) * rstd * gamma[tid]       + beta[tid];
    hr[tid + 256] = (v1 - mean) * rstd * gamma[tid + 256] + beta[tid + 256];
}

// ---------------------------------------------------------------------------
// tf32 tensor-core GEMM: C[M,512] = A[M,512] @ B[512,512] (+bias)(+resid)
// BM=128, BN=64, BK=16; 256 threads = 8 warps, each a 32x32 warp tile
// mma.sync.aligned.m16n8k8 tf32, double-buffered SMEM
// ---------------------------------------------------------------------------
__device__ __forceinline__ uint32_t f2tf(float x) {
    uint32_t u;
    asm("cvt.rna.tf32.f32 %0, %1;" : "=r"(u) : "f"(x));
    return u;
}

__device__ __forceinline__ void mma8(float* c, const uint32_t* a, const uint32_t* b) {
    asm volatile(
        "mma.sync.aligned.m16n8k8.row.col.f32.tf32.tf32.f32 "
        "{%0,%1,%2,%3}, {%4,%5,%6,%7}, {%8,%9}, {%0,%1,%2,%3};"
        : "+f"(c[0]), "+f"(c[1]), "+f"(c[2]), "+f"(c[3])
        : "r"(a[0]), "r"(a[1]), "r"(a[2]), "r"(a[3]), "r"(b[0]), "r"(b[1]));
}

template <bool RESID>
__device__ __forceinline__ void gemm_tf32(const float* __restrict__ A,
                                          const float* __restrict__ Bm,
                                          const float* __restrict__ bias,
                                          const float* __restrict__ resid,
                                          float* __restrict__ C,
                                          int bx, int by) {
    const int K = D_, N = D_;
    __shared__ uint32_t As[2][16][132];   // [buf][k][m], pad 4
    __shared__ uint32_t Bs[2][16][68];    // [buf][k][n], pad 4

    int tid = threadIdx.x;
    int lane = tid & 31, wid = tid >> 5;
    int wm = wid & 3, wn = wid >> 2;      // 4x2 warp grid
    int m0 = by * 128, n0 = bx * 64;

    float acc[2][4][4];
    #pragma unroll
    for (int mt = 0; mt < 2; mt++)
        #pragma unroll
        for (int nt = 0; nt < 4; nt++)
            #pragma unroll
            for (int i = 0; i < 4; i++) acc[mt][nt][i] = 0.f;

    // per-thread load coordinates
    int arow = tid >> 2;                  // 0..63 (two rows: arow, arow+64)
    int akq  = (tid & 3) << 2;            // 0,4,8,12
    int brow = tid >> 4;                  // 0..15
    int bnq  = (tid & 15) << 2;           // 0..60

    float4 ra0, ra1, rb;
    // prologue: tile 0
    ra0 = *(const float4*)(A + (size_t)(m0 + arow) * K + akq);
    ra1 = *(const float4*)(A + (size_t)(m0 + arow + 64) * K + akq);
    rb  = *(const float4*)(Bm + (size_t)brow * N + n0 + bnq);
    {
        As[0][akq + 0][arow] = f2tf(ra0.x);
        As[0][akq + 1][arow] = f2tf(ra0.y);
        As[0][akq + 2][arow] = f2tf(ra0.z);
        As[0][akq + 3][arow] = f2tf(ra0.w);
        As[0][akq + 0][arow + 64] = f2tf(ra1.x);
        As[0][akq + 1][arow + 64] = f2tf(ra1.y);
        As[0][akq + 2][arow + 64] = f2tf(ra1.z);
        As[0][akq + 3][arow + 64] = f2tf(ra1.w);
        uint4 bv = make_uint4(f2tf(rb.x), f2tf(rb.y), f2tf(rb.z), f2tf(rb.w));
        *(uint4*)&Bs[0][brow][bnq] = bv;
    }
    __syncthreads();

    const int NIT = K / 16;  // 32
    for (int it = 0; it < NIT; it++) {
        int buf = it & 1;
        if (it + 1 < NIT) {
            int k0 = (it + 1) * 16;
            ra0 = *(const float4*)(A + (size_t)(m0 + arow) * K + k0 + akq);
            ra1 = *(const float4*)(A + (size_t)(m0 + arow + 64) * K + k0 + akq);
            rb  = *(const float4*)(Bm + (size_t)(k0 + brow) * N + n0 + bnq);
        }
        // compute from smem buf
        #pragma unroll
        for (int ks = 0; ks < 2; ks++) {
            int kb = ks * 8 + (lane & 3);
            uint32_t a[2][4];
            #pragma unroll
            for (int mt = 0; mt < 2; mt++) {
                int m = wm * 32 + mt * 16 + (lane >> 2);
                a[mt][0] = As[buf][kb][m];
                a[mt][1] = As[buf][kb][m + 8];
                a[mt][2] = As[buf][kb + 4][m];
                a[mt][3] = As[buf][kb + 4][m + 8];
            }
            #pragma unroll
            for (int nt = 0; nt < 4; nt++) {
                uint32_t b[2];
                int n = wn * 32 + nt * 8 + (lane >> 2);
                b[0] = Bs[buf][kb][n];
                b[1] = Bs[buf][kb + 4][n];
                mma8(acc[0][nt], a[0], b);
                mma8(acc[1][nt], a[1], b);
            }
        }
        if (it + 1 < NIT) {
            int nb = (it + 1) & 1;
            As[nb][akq + 0][arow] = f2tf(ra0.x);
            As[nb][akq + 1][arow] = f2tf(ra0.y);
            As[nb][akq + 2][arow] = f2tf(ra0.z);
            As[nb][akq + 3][arow] = f2tf(ra0.w);
            As[nb][akq + 0][arow + 64] = f2tf(ra1.x);
            As[nb][akq + 1][arow + 64] = f2tf(ra1.y);
            As[nb][akq + 2][arow + 64] = f2tf(ra1.z);
            As[nb][akq + 3][arow + 64] = f2tf(ra1.w);
            uint4 bv = make_uint4(f2tf(rb.x), f2tf(rb.y), f2tf(rb.z), f2tf(rb.w));
            *(uint4*)&Bs[nb][brow][bnq] = bv;
        }
        __syncthreads();
    }

    // epilogue
    #pragma unroll
    for (int mt = 0; mt < 2; mt++) {
        #pragma unroll
        for (int nt = 0; nt < 4; nt++) {
            int r0 = m0 + wm * 32 + mt * 16 + (lane >> 2);
            int c  = n0 + wn * 32 + nt * 8 + (lane & 3) * 2;
            float b0 = bias[c], b1 = bias[c + 1];
            float2 o0 = make_float2(acc[mt][nt][0] + b0, acc[mt][nt][1] + b1);
            float2 o1 = make_float2(acc[mt][nt][2] + b0, acc[mt][nt][3] + b1);
            if (RESID) {
                float2 r0v = *(const float2*)(resid + (size_t)r0 * N + c);
                float2 r1v = *(const float2*)(resid + (size_t)(r0 + 8) * N + c);
                o0.x += r0v.x; o0.y += r0v.y;
                o1.x += r1v.x; o1.y += r1v.y;
            }
            *(float2*)(C + (size_t)r0 * N + c) = o0;
            *(float2*)(C + (size_t)(r0 + 8) * N + c) = o1;
        }
    }
}

__global__ __launch_bounds__(256) void qkv_kernel(const float* __restrict__ Wq,
                                                  const float* __restrict__ bq,
                                                  const float* __restrict__ Wk,
                                                  const float* __restrict__ bk,
                                                  const float* __restrict__ Wv,
                                                  const float* __restrict__ bv) {
    const float* W; const float* bi; float* C;
    if (blockIdx.z == 0)      { W = Wq; bi = bq; C = g_q; }
    else if (blockIdx.z == 1) { W = Wk; bi = bk; C = g_k; }
    else                      { W = Wv; bi = bv; C = g_v; }
    gemm_tf32<false>(g_h, W, bi, nullptr, C, blockIdx.x, blockIdx.y);
}

__global__ __launch_bounds__(256) void out_kernel(const float* __restrict__ Wo,
                                                  const float* __restrict__ bo,
                                                  const float* __restrict__ x,
                                                  float* __restrict__ out) {
    gemm_tf32<true>(g_ctx, Wo, bo, x, out, blockIdx.x, blockIdx.y);
}

// ---------------------------------------------------------------------------
// 3) Banded attention: one warp per (b,t,h); window [max(t-6,0), min(t+3,T-1)]
// ---------------------------------------------------------------------------
__global__ __launch_bounds__(256) void attn_kernel() {
    int gwarp = (blockIdx.x * blockDim.x + threadIdx.x) >> 5;
    int lane  = threadIdx.x & 31;
    int h  = gwarp & 7;
    int bt = gwarp >> 3;                 // 0..4095
    int b  = bt >> 11;
    int t  = bt & 2047;
    int lo = max(t - 6, 0);
    int hi = min(t + 3, T_ - 1);
    int nw = hi - lo + 1;                // <= 10

    const float* qp = g_q + (size_t)bt * D_ + h * DH_;
    float q0 = qp[lane], q1 = qp[lane + 32];

    float sc[10];
    float mx = -1e30f;
    for (int jj = 0; jj < nw; jj++) {
        int j = lo + jj;
        const float* kp = g_k + ((size_t)(b * T_ + j)) * D_ + h * DH_;
        float s = q0 * kp[lane] + q1 * kp[lane + 32];
        #pragma unroll
        for (int o = 16; o > 0; o >>= 1) s += __shfl_xor_sync(0xFFFFFFFFu, s, o);
        s *= 0.125f;                     // 1/sqrt(64)
        sc[jj] = s;
        mx = fmaxf(mx, s);
    }
    float denom = 0.f, c0 = 0.f, c1 = 0.f;
    for (int jj = 0; jj < nw; jj++) {
        int j = lo + jj;
        float p = __expf(sc[jj] - mx);
        denom += p;
        const float* vp = g_v + ((size_t)(b * T_ + j)) * D_ + h * DH_;
        c0 = fmaf(p, vp[lane],      c0);
        c1 = fmaf(p, vp[lane + 32], c1);
    }
    float inv = 1.f / denom;
    float* cp = g_ctx + (size_t)bt * D_ + h * DH_;
    cp[lane]      = c0 * inv;
    cp[lane + 32] = c1 * inv;
}

// ---------------------------------------------------------------------------
// Launch
// ---------------------------------------------------------------------------
extern "C" void kernel_launch(void* const* d_in, const int* in_sizes, int n_in,
                              void* d_out, int out_size) {
    const float* x     = (const float*)d_in[0];
    const float* gamma = (const float*)d_in[1];
    const float* beta  = (const float*)d_in[2];
    const float* Wq    = (const float*)d_in[3];
    const float* bq    = (const float*)d_in[4];
    const float* Wk    = (const float*)d_in[5];
    const float* bk    = (const float*)d_in[6];
    const float* Wv    = (const float*)d_in[7];
    const float* bv    = (const float*)d_in[8];
    const float* Wo    = (const float*)d_in[9];
    const float* bo    = (const float*)d_in[10];
    float* out = (float*)d_out;

    ln_kernel<<<M_, 256>>>(x, gamma, beta);
    qkv_kernel<<<dim3(D_/64, M_/128, 3), 256>>>(Wq, bq, Wk, bk, Wv, bv);
    attn_kernel<<<(M_*H_)/8, 256>>>();
    out_kernel<<<dim3(D_/64, M_/128), 256>>>(Wo, bo, x, out);
}

// round 3
// speedup vs baseline: 3.2714x; 2.0204x over previous
#include <cuda_runtime.h>
#include <cuda_bf16.h>
#include <math.h>
#include <stdint.h>

#define B_   2
#define T_   2048
#define D_   512
#define H_   8
#define DH_  64
#define M_   (B_*T_)   // 4096 token rows

// Scratch (no cudaMalloc allowed)
__device__ __nv_bfloat16 g_hb[M_*D_];        // LN output, bf16
__device__ __nv_bfloat16 g_wb[4*D_*D_];      // bf16 weights: q,k,v,o
__device__ float g_q[M_*D_];
__device__ float g_k[M_*D_];
__device__ float g_v[M_*D_];
__device__ __nv_bfloat16 g_ctxb[M_*D_];      // attention output, bf16

__device__ __forceinline__ uint32_t smem_u32(const void* p) {
    return (uint32_t)__cvta_generic_to_shared(p);
}

#define CP_ASYNC16(dst, src) \
    asm volatile("cp.async.cg.shared.global [%0], [%1], 16;" :: "r"(dst), "l"(src))
#define CP_COMMIT() asm volatile("cp.async.commit_group;")
#define CP_WAIT(n)  asm volatile("cp.async.wait_group %0;" :: "n"(n))

// ---------------------------------------------------------------------------
// 1) LayerNorm -> bf16 h
// ---------------------------------------------------------------------------
__global__ __launch_bounds__(256) void ln_kernel(const float* __restrict__ x,
                                                 const float* __restrict__ gamma,
                                                 const float* __restrict__ beta) {
    int row = blockIdx.x;
    int tid = threadIdx.x;
    const float* xr = x + (size_t)row * D_;
    float v0 = xr[tid], v1 = xr[tid + 256];
    float s  = v0 + v1;
    float s2 = v0 * v0 + v1 * v1;
    #pragma unroll
    for (int o = 16; o > 0; o >>= 1) {
        s  += __shfl_xor_sync(0xFFFFFFFFu, s,  o);
        s2 += __shfl_xor_sync(0xFFFFFFFFu, s2, o);
    }
    __shared__ float rs[8], rs2[8];
    int wid = tid >> 5, lane = tid & 31;
    if (lane == 0) { rs[wid] = s; rs2[wid] = s2; }
    __syncthreads();
    if (wid == 0) {
        s  = (lane < 8) ? rs[lane]  : 0.f;
        s2 = (lane < 8) ? rs2[lane] : 0.f;
        #pragma unroll
        for (int o = 4; o > 0; o >>= 1) {
            s  += __shfl_xor_sync(0xFFFFFFFFu, s,  o);
            s2 += __shfl_xor_sync(0xFFFFFFFFu, s2, o);
        }
        if (lane == 0) { rs[0] = s; rs2[0] = s2; }
    }
    __syncthreads();
    float mean = rs[0] * (1.0f / D_);
    float var  = rs2[0] * (1.0f / D_) - mean * mean;
    float rstd = rsqrtf(var + 1e-3f);
    __nv_bfloat16* hr = g_hb + (size_t)row * D_;
    hr[tid]       = __float2bfloat16_rn((v0 - mean) * rstd * gamma[tid]       + beta[tid]);
    hr[tid + 256] = __float2bfloat16_rn((v1 - mean) * rstd * gamma[tid + 256] + beta[tid + 256]);
}

// ---------------------------------------------------------------------------
// 1b) Weight conversion fp32 -> bf16 (Wq|Wk|Wv|Wo -> g_wb)
// ---------------------------------------------------------------------------
__global__ __launch_bounds__(256) void conv_kernel(const float* __restrict__ Wq,
                                                   const float* __restrict__ Wk,
                                                   const float* __restrict__ Wv,
                                                   const float* __restrict__ Wo) {
    size_t idx = ((size_t)blockIdx.x * 256 + threadIdx.x) * 4;   // 0..4*256K-1
    int m = (int)(idx >> 18);
    size_t off = idx & ((1u << 18) - 1);
    const float* src;
    if (m == 0) src = Wq; else if (m == 1) src = Wk; else if (m == 2) src = Wv; else src = Wo;
    float4 v = *(const float4*)(src + off);
    __nv_bfloat162 lo = __floats2bfloat162_rn(v.x, v.y);
    __nv_bfloat162 hi = __floats2bfloat162_rn(v.z, v.w);
    *(__nv_bfloat162*)(g_wb + idx)     = lo;
    *(__nv_bfloat162*)(g_wb + idx + 2) = hi;
}

// ---------------------------------------------------------------------------
// bf16 tensor-core GEMM: C[M,512] = A[M,512](bf16) @ B[512,512](bf16) (+bias)(+resid)
// BM=128, BN=64, BK=32; 8 warps, warp tile 32x32; m16n8k16; cp.async pipeline
// ---------------------------------------------------------------------------
#define APAD 40   // 32 + 8 bf16 row stride (conflict-free ldmatrix)
#define BPAD 72   // 64 + 8

__device__ __forceinline__ void mma16(float* c, const uint32_t* a, const uint32_t* b) {
    asm volatile(
        "mma.sync.aligned.m16n8k16.row.col.f32.bf16.bf16.f32 "
        "{%0,%1,%2,%3}, {%4,%5,%6,%7}, {%8,%9}, {%0,%1,%2,%3};"
        : "+f"(c[0]), "+f"(c[1]), "+f"(c[2]), "+f"(c[3])
        : "r"(a[0]), "r"(a[1]), "r"(a[2]), "r"(a[3]), "r"(b[0]), "r"(b[1]));
}

template <bool RESID>
__device__ __forceinline__ void gemm_bf16(const __nv_bfloat16* __restrict__ A,
                                          const __nv_bfloat16* __restrict__ Bm,
                                          const float* __restrict__ bias,
                                          const float* __restrict__ resid,
                                          float* __restrict__ C,
                                          int bx, int by) {
    const int K = D_, N = D_;
    __shared__ __nv_bfloat16 As[2][128][APAD];
    __shared__ __nv_bfloat16 Bs[2][32][BPAD];

    int tid = threadIdx.x;
    int lane = tid & 31, wid = tid >> 5;
    int wm = wid & 3, wn = wid >> 2;      // 4x2 warp grid -> 32x32 warp tiles
    int m0 = by * 128, n0 = bx * 64;

    float acc[2][4][4];
    #pragma unroll
    for (int mt = 0; mt < 2; mt++)
        #pragma unroll
        for (int nt = 0; nt < 4; nt++)
            #pragma unroll
            for (int i = 0; i < 4; i++) acc[mt][nt][i] = 0.f;

    // cp.async coordinates
    int ar = tid >> 2;            // 0..63 (rows ar, ar+64)
    int ac = (tid & 3) * 8;       // bf16 col within BK
    int br = tid >> 3;            // 0..31
    int bc = (tid & 7) * 8;

    uint32_t sA = smem_u32(&As[0][0][0]);
    uint32_t sB = smem_u32(&Bs[0][0][0]);
    const uint32_t ABUF = 128 * APAD * 2;     // bytes per A buffer
    const uint32_t BBUF = 32 * BPAD * 2;

    uint32_t dA0 = sA + (ar * APAD + ac) * 2;
    uint32_t dA1 = sA + ((ar + 64) * APAD + ac) * 2;
    uint32_t dB  = sB + (br * BPAD + bc) * 2;

    const __nv_bfloat16* gA0 = A + (size_t)(m0 + ar) * K + ac;
    const __nv_bfloat16* gA1 = A + (size_t)(m0 + ar + 64) * K + ac;
    const __nv_bfloat16* gB  = Bm + (size_t)br * N + n0 + bc;

    // prologue: tile 0
    CP_ASYNC16(dA0, gA0);
    CP_ASYNC16(dA1, gA1);
    CP_ASYNC16(dB,  gB);
    CP_COMMIT();

    const int NIT = K / 32;   // 16
    for (int it = 0; it < NIT; it++) {
        int buf = it & 1;
        if (it + 1 < NIT) {
            int nb = (it + 1) & 1;
            int k0 = (it + 1) * 32;
            CP_ASYNC16(dA0 + nb * ABUF, gA0 + k0);
            CP_ASYNC16(dA1 + nb * ABUF, gA1 + k0);
            CP_ASYNC16(dB  + nb * BBUF, gB + (size_t)k0 * N);
            CP_COMMIT();
            CP_WAIT(1);
        } else {
            CP_WAIT(0);
        }
        __syncthreads();

        uint32_t aBase = sA + buf * ABUF;
        uint32_t bBase = sB + buf * BBUF;
        #pragma unroll
        for (int ks = 0; ks < 2; ks++) {
            int kq = ks * 16;
            uint32_t a[2][4], bf[2][4];
            #pragma unroll
            for (int mt = 0; mt < 2; mt++) {
                int row = wm * 32 + mt * 16 + (lane & 15);
                int col = kq + ((lane >> 4) * 8);
                uint32_t addr = aBase + (row * APAD + col) * 2;
                asm volatile("ldmatrix.sync.aligned.m8n8.x4.shared.b16 {%0,%1,%2,%3}, [%4];"
                             : "=r"(a[mt][0]), "=r"(a[mt][1]), "=r"(a[mt][2]), "=r"(a[mt][3])
                             : "r"(addr));
            }
            #pragma unroll
            for (int np = 0; np < 2; np++) {
                int row = kq + (lane & 15);
                int col = wn * 32 + np * 16 + ((lane >> 4) * 8);
                uint32_t addr = bBase + (row * BPAD + col) * 2;
                asm volatile("ldmatrix.sync.aligned.m8n8.x4.trans.shared.b16 {%0,%1,%2,%3}, [%4];"
                             : "=r"(bf[np][0]), "=r"(bf[np][1]), "=r"(bf[np][2]), "=r"(bf[np][3])
                             : "r"(addr));
            }
            #pragma unroll
            for (int mt = 0; mt < 2; mt++)
                #pragma unroll
                for (int nt = 0; nt < 4; nt++)
                    mma16(acc[mt][nt], a[mt], &bf[nt >> 1][(nt & 1) * 2]);
        }
        __syncthreads();
    }

    // epilogue
    #pragma unroll
    for (int mt = 0; mt < 2; mt++) {
        #pragma unroll
        for (int nt = 0; nt < 4; nt++) {
            int r0 = m0 + wm * 32 + mt * 16 + (lane >> 2);
            int c  = n0 + wn * 32 + nt * 8 + (lane & 3) * 2;
            float b0 = bias[c], b1 = bias[c + 1];
            float2 o0 = make_float2(acc[mt][nt][0] + b0, acc[mt][nt][1] + b1);
            float2 o1 = make_float2(acc[mt][nt][2] + b0, acc[mt][nt][3] + b1);
            if (RESID) {
                float2 r0v = *(const float2*)(resid + (size_t)r0 * D_ + c);
                float2 r1v = *(const float2*)(resid + (size_t)(r0 + 8) * D_ + c);
                o0.x += r0v.x; o0.y += r0v.y;
                o1.x += r1v.x; o1.y += r1v.y;
            }
            *(float2*)(C + (size_t)r0 * D_ + c) = o0;
            *(float2*)(C + (size_t)(r0 + 8) * D_ + c) = o1;
        }
    }
}

__global__ __launch_bounds__(256) void qkv_kernel(const float* __restrict__ bq,
                                                  const float* __restrict__ bk,
                                                  const float* __restrict__ bv) {
    const float* bi; float* C;
    if (blockIdx.z == 0)      { bi = bq; C = g_q; }
    else if (blockIdx.z == 1) { bi = bk; C = g_k; }
    else                      { bi = bv; C = g_v; }
    const __nv_bfloat16* W = g_wb + (size_t)blockIdx.z * D_ * D_;
    gemm_bf16<false>(g_hb, W, bi, nullptr, C, blockIdx.x, blockIdx.y);
}

__global__ __launch_bounds__(256) void out_kernel(const float* __restrict__ bo,
                                                  const float* __restrict__ x,
                                                  float* __restrict__ out) {
    gemm_bf16<true>(g_ctxb, g_wb + (size_t)3 * D_ * D_, bo, x, out, blockIdx.x, blockIdx.y);
}

// ---------------------------------------------------------------------------
// 3) Banded attention: one warp per (b,t,h); window [max(t-6,0), min(t+3,T-1)]
// ---------------------------------------------------------------------------
__global__ __launch_bounds__(256) void attn_kernel() {
    int gwarp = (blockIdx.x * blockDim.x + threadIdx.x) >> 5;
    int lane  = threadIdx.x & 31;
    int h  = gwarp & 7;
    int bt = gwarp >> 3;
    int b  = bt >> 11;
    int t  = bt & 2047;
    int lo = max(t - 6, 0);
    int hi = min(t + 3, T_ - 1);
    int nw = hi - lo + 1;                // <= 10

    const float* qp = g_q + (size_t)bt * D_ + h * DH_;
    float q0 = qp[lane] * 0.125f, q1 = qp[lane + 32] * 0.125f;

    float sc[10];
    float mx = -1e30f;
    for (int jj = 0; jj < nw; jj++) {
        int j = lo + jj;
        const float* kp = g_k + ((size_t)(b * T_ + j)) * D_ + h * DH_;
        float s = q0 * kp[lane] + q1 * kp[lane + 32];
        #pragma unroll
        for (int o = 16; o > 0; o >>= 1) s += __shfl_xor_sync(0xFFFFFFFFu, s, o);
        sc[jj] = s;
        mx = fmaxf(mx, s);
    }
    float denom = 0.f, c0 = 0.f, c1 = 0.f;
    for (int jj = 0; jj < nw; jj++) {
        int j = lo + jj;
        float p = __expf(sc[jj] - mx);
        denom += p;
        const float* vp = g_v + ((size_t)(b * T_ + j)) * D_ + h * DH_;
        c0 = fmaf(p, vp[lane],      c0);
        c1 = fmaf(p, vp[lane + 32], c1);
    }
    float inv = 1.f / denom;
    __nv_bfloat16* cp = g_ctxb + (size_t)bt * D_ + h * DH_;
    cp[lane]      = __float2bfloat16_rn(c0 * inv);
    cp[lane + 32] = __float2bfloat16_rn(c1 * inv);
}

// ---------------------------------------------------------------------------
// Launch
// ---------------------------------------------------------------------------
extern "C" void kernel_launch(void* const* d_in, const int* in_sizes, int n_in,
                              void* d_out, int out_size) {
    const float* x     = (const float*)d_in[0];
    const float* gamma = (const float*)d_in[1];
    const float* beta  = (const float*)d_in[2];
    const float* Wq    = (const float*)d_in[3];
    const float* bq    = (const float*)d_in[4];
    const float* Wk    = (const float*)d_in[5];
    const float* bk    = (const float*)d_in[6];
    const float* Wv    = (const float*)d_in[7];
    const float* bv    = (const float*)d_in[8];
    const float* Wo    = (const float*)d_in[9];
    const float* bo    = (const float*)d_in[10];
    float* out = (float*)d_out;

    conv_kernel<<<(4 * D_ * D_) / (256 * 4), 256>>>(Wq, Wk, Wv, Wo);
    ln_kernel<<<M_, 256>>>(x, gamma, beta);
    qkv_kernel<<<dim3(D_/64, M_/128, 3), 256>>>(bq, bk, bv);
    attn_kernel<<<(M_*H_)/8, 256>>>();
    out_kernel<<<dim3(D_/64, M_/128), 256>>>(bo, x, out);
}

// round 4
// speedup vs baseline: 3.5483x; 1.0847x over previous
#include <cuda_runtime.h>
#include <cuda_bf16.h>
#include <math.h>
#include <stdint.h>

#define B_   2
#define T_   2048
#define D_   512
#define H_   8
#define DH_  64
#define M_   (B_*T_)   // 4096 token rows

// Scratch (no cudaMalloc allowed)
__device__ __nv_bfloat16 g_hb[M_*D_];        // LN output, bf16
__device__ __nv_bfloat16 g_wb[4*D_*D_];      // bf16 weights: q,k,v,o
__device__ float g_q[M_*D_];
__device__ float g_k[M_*D_];
__device__ float g_v[M_*D_];
__device__ __nv_bfloat16 g_ctxb[M_*D_];      // attention output, bf16

__device__ __forceinline__ uint32_t smem_u32(const void* p) {
    return (uint32_t)__cvta_generic_to_shared(p);
}

#define CP_ASYNC16(dst, src) \
    asm volatile("cp.async.cg.shared.global [%0], [%1], 16;" :: "r"(dst), "l"(src))
#define CP_COMMIT() asm volatile("cp.async.commit_group;")
#define CP_WAIT(n)  asm volatile("cp.async.wait_group %0;" :: "n"(n))

// ---------------------------------------------------------------------------
// 1) LayerNorm -> bf16 h
// ---------------------------------------------------------------------------
__global__ __launch_bounds__(256) void ln_kernel(const float* __restrict__ x,
                                                 const float* __restrict__ gamma,
                                                 const float* __restrict__ beta) {
    int row = blockIdx.x;
    int tid = threadIdx.x;
    const float* xr = x + (size_t)row * D_;
    float v0 = xr[tid], v1 = xr[tid + 256];
    float s  = v0 + v1;
    float s2 = v0 * v0 + v1 * v1;
    #pragma unroll
    for (int o = 16; o > 0; o >>= 1) {
        s  += __shfl_xor_sync(0xFFFFFFFFu, s,  o);
        s2 += __shfl_xor_sync(0xFFFFFFFFu, s2, o);
    }
    __shared__ float rs[8], rs2[8];
    int wid = tid >> 5, lane = tid & 31;
    if (lane == 0) { rs[wid] = s; rs2[wid] = s2; }
    __syncthreads();
    if (wid == 0) {
        s  = (lane < 8) ? rs[lane]  : 0.f;
        s2 = (lane < 8) ? rs2[lane] : 0.f;
        #pragma unroll
        for (int o = 4; o > 0; o >>= 1) {
            s  += __shfl_xor_sync(0xFFFFFFFFu, s,  o);
            s2 += __shfl_xor_sync(0xFFFFFFFFu, s2, o);
        }
        if (lane == 0) { rs[0] = s; rs2[0] = s2; }
    }
    __syncthreads();
    float mean = rs[0] * (1.0f / D_);
    float var  = rs2[0] * (1.0f / D_) - mean * mean;
    float rstd = rsqrtf(var + 1e-3f);
    __nv_bfloat16* hr = g_hb + (size_t)row * D_;
    hr[tid]       = __float2bfloat16_rn((v0 - mean) * rstd * gamma[tid]       + beta[tid]);
    hr[tid + 256] = __float2bfloat16_rn((v1 - mean) * rstd * gamma[tid + 256] + beta[tid + 256]);
}

// ---------------------------------------------------------------------------
// 1b) Weight conversion fp32 -> bf16 (Wq|Wk|Wv|Wo -> g_wb)
// ---------------------------------------------------------------------------
__global__ __launch_bounds__(256) void conv_kernel(const float* __restrict__ Wq,
                                                   const float* __restrict__ Wk,
                                                   const float* __restrict__ Wv,
                                                   const float* __restrict__ Wo) {
    size_t idx = ((size_t)blockIdx.x * 256 + threadIdx.x) * 4;
    int m = (int)(idx >> 18);
    size_t off = idx & ((1u << 18) - 1);
    const float* src;
    if (m == 0) src = Wq; else if (m == 1) src = Wk; else if (m == 2) src = Wv; else src = Wo;
    float4 v = *(const float4*)(src + off);
    __nv_bfloat162 lo = __floats2bfloat162_rn(v.x, v.y);
    __nv_bfloat162 hi = __floats2bfloat162_rn(v.z, v.w);
    *(__nv_bfloat162*)(g_wb + idx)     = lo;
    *(__nv_bfloat162*)(g_wb + idx + 2) = hi;
}

// ---------------------------------------------------------------------------
// bf16 tensor-core GEMM: C[M,512] = A[M,512](bf16) @ B[512,512](bf16) (+bias)(+resid)
// ---------------------------------------------------------------------------
#define APAD 40
#define BPAD 72

__device__ __forceinline__ void mma16(float* c, const uint32_t* a, const uint32_t* b) {
    asm volatile(
        "mma.sync.aligned.m16n8k16.row.col.f32.bf16.bf16.f32 "
        "{%0,%1,%2,%3}, {%4,%5,%6,%7}, {%8,%9}, {%0,%1,%2,%3};"
        : "+f"(c[0]), "+f"(c[1]), "+f"(c[2]), "+f"(c[3])
        : "r"(a[0]), "r"(a[1]), "r"(a[2]), "r"(a[3]), "r"(b[0]), "r"(b[1]));
}

template <bool RESID>
__device__ __forceinline__ void gemm_bf16(const __nv_bfloat16* __restrict__ A,
                                          const __nv_bfloat16* __restrict__ Bm,
                                          const float* __restrict__ bias,
                                          const float* __restrict__ resid,
                                          float* __restrict__ C,
                                          int bx, int by) {
    const int K = D_, N = D_;
    __shared__ __nv_bfloat16 As[2][128][APAD];
    __shared__ __nv_bfloat16 Bs[2][32][BPAD];

    int tid = threadIdx.x;
    int lane = tid & 31, wid = tid >> 5;
    int wm = wid & 3, wn = wid >> 2;
    int m0 = by * 128, n0 = bx * 64;

    float acc[2][4][4];
    #pragma unroll
    for (int mt = 0; mt < 2; mt++)
        #pragma unroll
        for (int nt = 0; nt < 4; nt++)
            #pragma unroll
            for (int i = 0; i < 4; i++) acc[mt][nt][i] = 0.f;

    int ar = tid >> 2;
    int ac = (tid & 3) * 8;
    int br = tid >> 3;
    int bc = (tid & 7) * 8;

    uint32_t sA = smem_u32(&As[0][0][0]);
    uint32_t sB = smem_u32(&Bs[0][0][0]);
    const uint32_t ABUF = 128 * APAD * 2;
    const uint32_t BBUF = 32 * BPAD * 2;

    uint32_t dA0 = sA + (ar * APAD + ac) * 2;
    uint32_t dA1 = sA + ((ar + 64) * APAD + ac) * 2;
    uint32_t dB  = sB + (br * BPAD + bc) * 2;

    const __nv_bfloat16* gA0 = A + (size_t)(m0 + ar) * K + ac;
    const __nv_bfloat16* gA1 = A + (size_t)(m0 + ar + 64) * K + ac;
    const __nv_bfloat16* gB  = Bm + (size_t)br * N + n0 + bc;

    CP_ASYNC16(dA0, gA0);
    CP_ASYNC16(dA1, gA1);
    CP_ASYNC16(dB,  gB);
    CP_COMMIT();

    const int NIT = K / 32;
    for (int it = 0; it < NIT; it++) {
        int buf = it & 1;
        if (it + 1 < NIT) {
            int nb = (it + 1) & 1;
            int k0 = (it + 1) * 32;
            CP_ASYNC16(dA0 + nb * ABUF, gA0 + k0);
            CP_ASYNC16(dA1 + nb * ABUF, gA1 + k0);
            CP_ASYNC16(dB  + nb * BBUF, gB + (size_t)k0 * N);
            CP_COMMIT();
            CP_WAIT(1);
        } else {
            CP_WAIT(0);
        }
        __syncthreads();

        uint32_t aBase = sA + buf * ABUF;
        uint32_t bBase = sB + buf * BBUF;
        #pragma unroll
        for (int ks = 0; ks < 2; ks++) {
            int kq = ks * 16;
            uint32_t a[2][4], bf[2][4];
            #pragma unroll
            for (int mt = 0; mt < 2; mt++) {
                int row = wm * 32 + mt * 16 + (lane & 15);
                int col = kq + ((lane >> 4) * 8);
                uint32_t addr = aBase + (row * APAD + col) * 2;
                asm volatile("ldmatrix.sync.aligned.m8n8.x4.shared.b16 {%0,%1,%2,%3}, [%4];"
                             : "=r"(a[mt][0]), "=r"(a[mt][1]), "=r"(a[mt][2]), "=r"(a[mt][3])
                             : "r"(addr));
            }
            #pragma unroll
            for (int np = 0; np < 2; np++) {
                int row = kq + (lane & 15);
                int col = wn * 32 + np * 16 + ((lane >> 4) * 8);
                uint32_t addr = bBase + (row * BPAD + col) * 2;
                asm volatile("ldmatrix.sync.aligned.m8n8.x4.trans.shared.b16 {%0,%1,%2,%3}, [%4];"
                             : "=r"(bf[np][0]), "=r"(bf[np][1]), "=r"(bf[np][2]), "=r"(bf[np][3])
                             : "r"(addr));
            }
            #pragma unroll
            for (int mt = 0; mt < 2; mt++)
                #pragma unroll
                for (int nt = 0; nt < 4; nt++)
                    mma16(acc[mt][nt], a[mt], &bf[nt >> 1][(nt & 1) * 2]);
        }
        __syncthreads();
    }

    #pragma unroll
    for (int mt = 0; mt < 2; mt++) {
        #pragma unroll
        for (int nt = 0; nt < 4; nt++) {
            int r0 = m0 + wm * 32 + mt * 16 + (lane >> 2);
            int c  = n0 + wn * 32 + nt * 8 + (lane & 3) * 2;
            float b0 = bias[c], b1 = bias[c + 1];
            float2 o0 = make_float2(acc[mt][nt][0] + b0, acc[mt][nt][1] + b1);
            float2 o1 = make_float2(acc[mt][nt][2] + b0, acc[mt][nt][3] + b1);
            if (RESID) {
                float2 r0v = *(const float2*)(resid + (size_t)r0 * D_ + c);
                float2 r1v = *(const float2*)(resid + (size_t)(r0 + 8) * D_ + c);
                o0.x += r0v.x; o0.y += r0v.y;
                o1.x += r1v.x; o1.y += r1v.y;
            }
            *(float2*)(C + (size_t)r0 * D_ + c) = o0;
            *(float2*)(C + (size_t)(r0 + 8) * D_ + c) = o1;
        }
    }
}

__global__ __launch_bounds__(256) void qkv_kernel(const float* __restrict__ bq,
                                                  const float* __restrict__ bk,
                                                  const float* __restrict__ bv) {
    const float* bi; float* C;
    if (blockIdx.z == 0)      { bi = bq; C = g_q; }
    else if (blockIdx.z == 1) { bi = bk; C = g_k; }
    else                      { bi = bv; C = g_v; }
    const __nv_bfloat16* W = g_wb + (size_t)blockIdx.z * D_ * D_;
    gemm_bf16<false>(g_hb, W, bi, nullptr, C, blockIdx.x, blockIdx.y);
}

__global__ __launch_bounds__(256) void out_kernel(const float* __restrict__ bo,
                                                  const float* __restrict__ x,
                                                  float* __restrict__ out) {
    gemm_bf16<true>(g_ctxb, g_wb + (size_t)3 * D_ * D_, bo, x, out, blockIdx.x, blockIdx.y);
}

// ---------------------------------------------------------------------------
// 3) Banded attention, tiled: block = one (b,h) x 32 queries.
//    K/V window (41 rows x 64) staged in SMEM once; warp = 4 queries,
//    8-lane groups, each lane owns 8 head dims (2 float4).
// ---------------------------------------------------------------------------
#define TQ 32
#define WROWS (TQ + 9)   // 41
#define KVPAD 68

__global__ __launch_bounds__(256) void attn_kernel() {
    __shared__ float Ks[WROWS][KVPAD];
    __shared__ float Vs[WROWS][KVPAD];

    int bh = blockIdx.y;
    int b = bh >> 3, h = bh & 7;
    int t0 = blockIdx.x * TQ;
    int tid = threadIdx.x;

    // cooperative load: 41 rows x 16 float4 (K and V)
    for (int idx = tid; idx < WROWS * 16; idx += 256) {
        int r = idx >> 4;
        int c4 = (idx & 15) * 4;
        int jg = t0 - 6 + r;
        if (jg >= 0 && jg < T_) {
            size_t base = ((size_t)(b * T_ + jg)) * D_ + h * DH_ + c4;
            *(float4*)&Ks[r][c4] = *(const float4*)(g_k + base);
            *(float4*)&Vs[r][c4] = *(const float4*)(g_v + base);
        } else {
            float4 z = make_float4(0.f, 0.f, 0.f, 0.f);
            *(float4*)&Ks[r][c4] = z;
            *(float4*)&Vs[r][c4] = z;
        }
    }
    __syncthreads();

    int w = tid >> 5, lane = tid & 31;
    int sub = lane >> 3, di = lane & 7;       // 4 query groups x 8 dim-lanes
    int t = t0 + w * 4 + sub;
    int lo = max(t - 6, 0);
    int hi = min(t + 3, T_ - 1);
    int nw = hi - lo + 1;                     // <= 10
    int rbase = lo - (t0 - 6);                // SMEM row of jj=0

    const float* qp = g_q + ((size_t)(b * T_ + t)) * D_ + h * DH_ + di * 8;
    float4 qa = *(const float4*)qp;
    float4 qb = *(const float4*)(qp + 4);
    qa.x *= 0.125f; qa.y *= 0.125f; qa.z *= 0.125f; qa.w *= 0.125f;
    qb.x *= 0.125f; qb.y *= 0.125f; qb.z *= 0.125f; qb.w *= 0.125f;

    float sc[10];
    float mx = -1e30f;
    #pragma unroll
    for (int jj = 0; jj < 10; jj++) {
        int r = rbase + jj;                   // always < WROWS (rows zero-filled OOB)
        const float* kr = &Ks[r][di * 8];
        float4 k0 = *(const float4*)kr;
        float4 k1 = *(const float4*)(kr + 4);
        float s = qa.x * k0.x + qa.y * k0.y + qa.z * k0.z + qa.w * k0.w
                + qb.x * k1.x + qb.y * k1.y + qb.z * k1.z + qb.w * k1.w;
        s += __shfl_xor_sync(0xFFFFFFFFu, s, 4);
        s += __shfl_xor_sync(0xFFFFFFFFu, s, 2);
        s += __shfl_xor_sync(0xFFFFFFFFu, s, 1);
        s = (jj < nw) ? s : -1e30f;
        sc[jj] = s;
        mx = fmaxf(mx, s);
    }

    float denom = 0.f;
    float a0 = 0.f, a1 = 0.f, a2 = 0.f, a3 = 0.f;
    float a4 = 0.f, a5 = 0.f, a6 = 0.f, a7 = 0.f;
    #pragma unroll
    for (int jj = 0; jj < 10; jj++) {
        float p = __expf(sc[jj] - mx);        // 0 for invalid jj
        denom += p;
        int r = rbase + jj;
        const float* vr = &Vs[r][di * 8];     // zero-filled OOB rows: p*0 safe
        float4 v0 = *(const float4*)vr;
        float4 v1 = *(const float4*)(vr + 4);
        a0 = fmaf(p, v0.x, a0); a1 = fmaf(p, v0.y, a1);
        a2 = fmaf(p, v0.z, a2); a3 = fmaf(p, v0.w, a3);
        a4 = fmaf(p, v1.x, a4); a5 = fmaf(p, v1.y, a5);
        a6 = fmaf(p, v1.z, a6); a7 = fmaf(p, v1.w, a7);
    }
    float inv = 1.f / denom;

    __nv_bfloat162 o0 = __floats2bfloat162_rn(a0 * inv, a1 * inv);
    __nv_bfloat162 o1 = __floats2bfloat162_rn(a2 * inv, a3 * inv);
    __nv_bfloat162 o2 = __floats2bfloat162_rn(a4 * inv, a5 * inv);
    __nv_bfloat162 o3 = __floats2bfloat162_rn(a6 * inv, a7 * inv);
    uint4 pack;
    pack.x = *(uint32_t*)&o0; pack.y = *(uint32_t*)&o1;
    pack.z = *(uint32_t*)&o2; pack.w = *(uint32_t*)&o3;
    *(uint4*)(g_ctxb + ((size_t)(b * T_ + t)) * D_ + h * DH_ + di * 8) = pack;
}

// ---------------------------------------------------------------------------
// Launch
// ---------------------------------------------------------------------------
extern "C" void kernel_launch(void* const* d_in, const int* in_sizes, int n_in,
                              void* d_out, int out_size) {
    const float* x     = (const float*)d_in[0];
    const float* gamma = (const float*)d_in[1];
    const float* beta  = (const float*)d_in[2];
    const float* Wq    = (const float*)d_in[3];
    const float* bq    = (const float*)d_in[4];
    const float* Wk    = (const float*)d_in[5];
    const float* bk    = (const float*)d_in[6];
    const float* Wv    = (const float*)d_in[7];
    const float* bv    = (const float*)d_in[8];
    const float* Wo    = (const float*)d_in[9];
    const float* bo    = (const float*)d_in[10];
    float* out = (float*)d_out;

    conv_kernel<<<(4 * D_ * D_) / (256 * 4), 256>>>(Wq, Wk, Wv, Wo);
    ln_kernel<<<M_, 256>>>(x, gamma, beta);
    qkv_kernel<<<dim3(D_/64, M_/128, 3), 256>>>(bq, bk, bv);
    attn_kernel<<<dim3(T_/TQ, B_*H_), 256>>>();
    out_kernel<<<dim3(D_/64, M_/128), 256>>>(bo, x, out);
}